// round 9
// baseline (speedup 1.0000x reference)
#include <cuda_runtime.h>
#include <math.h>

#define S_    2048
#define HID_  2048
#define H_    16
#define NOPE_ 128
#define ROPE_ 64
#define VDIM_ 128
#define QR_   1536
#define KVR_  512
#define IH_   16
#define ID_   128
#define TOPK_ 512
#define EPS_  1e-6f
#define CKVW_ (KVR_ + ROPE_)

// ---------------- scratch ----------------
__device__ float g_qr    [S_*QR_];
__device__ float g_q     [S_*H_*(NOPE_+ROPE_)];
__device__ float g_ckv   [S_*CKVW_];
__device__ float g_ckvn  [S_*KVR_];
__device__ float g_kpe   [S_*ROPE_];
__device__ float g_kv    [S_*H_*(NOPE_+VDIM_)];
__device__ float g_iq    [S_*IH_*ID_];
__device__ float g_ikpre [S_*ID_];
__device__ float g_ik    [S_*ID_];
__device__ float g_iw    [S_*IH_];
__device__ float g_scores[S_*S_];
__device__ int   g_sel   [S_*TOPK_];
__device__ int   g_nsel  [S_];
__device__ float g_attn  [S_*H_*VDIM_];
__device__ float g_cosb  [S_*32];
__device__ float g_sinb  [S_*32];

// ---------------- helpers ----------------
__device__ __forceinline__ float blockReduceSum(float v, float* sh) {
    int lane = threadIdx.x & 31, w = threadIdx.x >> 5;
    #pragma unroll
    for (int o = 16; o; o >>= 1) v += __shfl_xor_sync(0xffffffffu, v, o);
    if (lane == 0) sh[w] = v;
    __syncthreads();
    int nw = (blockDim.x + 31) >> 5;
    float r = (threadIdx.x < nw) ? sh[threadIdx.x] : 0.f;
    if (w == 0) {
        #pragma unroll
        for (int o = 16; o; o >>= 1) r += __shfl_xor_sync(0xffffffffu, r, o);
        if (lane == 0) sh[0] = r;
    }
    __syncthreads();
    float out = sh[0];
    __syncthreads();
    return out;
}

// ---------------- cos/sin (bit-exact numpy float32 path) ----------------
__global__ void cossin_kernel() {
    int s = blockIdx.x, d = threadIdx.x;
    float e = (float)(2 * d) / 64.0f;
    float pf = (float)pow(10000.0, (double)e);
    float inv = __fdiv_rn(1.0f, pf);
    float f = __fmul_rn((float)s, inv);
    g_cosb[s * 32 + d] = (float)cos((double)f);
    g_sinb[s * 32 + d] = (float)sin((double)f);
}

// ============ shared GEMM body: 128x128 tile, conflict-free quadrant microtile ============
// Scalar FFMA inner loop (rt2, full-rate pipe). Per-output accumulation is strictly
// k-ascending with a single accumulator -> bit-identical across callers/tilings.
__device__ __forceinline__ void gemm_body_128(
    const float* __restrict__ A, int lda,
    const float* __restrict__ B, int ldb,
    float* __restrict__ C, int ldc,
    int M, int N, int K, float alpha,
    int m0, int n0,
    float (*As)[8][128], float (*Bs)[8][128])
{
    int t = threadIdx.x;
    int tx = t & 15, ty = t >> 4;
    int a_m = t >> 1, a_k = (t & 1) * 4;
    int gmA = m0 + a_m, gnB = n0 + a_m;
    float acc[8][8];
    #pragma unroll
    for (int i = 0; i < 8; i++)
        #pragma unroll
        for (int j = 0; j < 8; j++) acc[i][j] = 0.f;

    float4 va = make_float4(0.f,0.f,0.f,0.f), vb = va;
    if (gmA < M) va = *reinterpret_cast<const float4*>(&A[(size_t)gmA * lda + a_k]);
    if (gnB < N) vb = *reinterpret_cast<const float4*>(&B[(size_t)gnB * ldb + a_k]);
    As[0][a_k+0][a_m]=va.x; As[0][a_k+1][a_m]=va.y; As[0][a_k+2][a_m]=va.z; As[0][a_k+3][a_m]=va.w;
    Bs[0][a_k+0][a_m]=vb.x; Bs[0][a_k+1][a_m]=vb.y; Bs[0][a_k+2][a_m]=vb.z; Bs[0][a_k+3][a_m]=vb.w;
    __syncthreads();
    int buf = 0;
    for (int k0 = 0; k0 < K; k0 += 8) {
        bool nxt = (k0 + 8) < K;
        if (nxt) {
            va = make_float4(0.f,0.f,0.f,0.f); vb = va;
            if (gmA < M) va = *reinterpret_cast<const float4*>(&A[(size_t)gmA * lda + k0 + 8 + a_k]);
            if (gnB < N) vb = *reinterpret_cast<const float4*>(&B[(size_t)gnB * ldb + k0 + 8 + a_k]);
        }
        #pragma unroll
        for (int k = 0; k < 8; k++) {
            float4 a0 = *reinterpret_cast<const float4*>(&As[buf][k][ty * 4]);
            float4 a1 = *reinterpret_cast<const float4*>(&As[buf][k][64 + ty * 4]);
            float4 b0 = *reinterpret_cast<const float4*>(&Bs[buf][k][tx * 4]);
            float4 b1 = *reinterpret_cast<const float4*>(&Bs[buf][k][64 + tx * 4]);
            float ra[8] = {a0.x,a0.y,a0.z,a0.w,a1.x,a1.y,a1.z,a1.w};
            float rb[8] = {b0.x,b0.y,b0.z,b0.w,b1.x,b1.y,b1.z,b1.w};
            #pragma unroll
            for (int i = 0; i < 8; i++)
                #pragma unroll
                for (int j = 0; j < 8; j++) acc[i][j] += ra[i] * rb[j];
        }
        if (nxt) {
            int nb = buf ^ 1;
            As[nb][a_k+0][a_m]=va.x; As[nb][a_k+1][a_m]=va.y; As[nb][a_k+2][a_m]=va.z; As[nb][a_k+3][a_m]=va.w;
            Bs[nb][a_k+0][a_m]=vb.x; Bs[nb][a_k+1][a_m]=vb.y; Bs[nb][a_k+2][a_m]=vb.z; Bs[nb][a_k+3][a_m]=vb.w;
            __syncthreads();
            buf = nb;
        }
    }
    #pragma unroll
    for (int i = 0; i < 8; i++) {
        int gm = m0 + ((i < 4) ? (ty * 4 + i) : (64 + ty * 4 + i - 4));
        if (gm >= M) continue;
        #pragma unroll
        for (int j = 0; j < 8; j++) {
            int gn = n0 + ((j < 4) ? (tx * 4 + j) : (64 + tx * 4 + j - 4));
            if (gn < N) C[(size_t)gm * ldc + gn] = alpha * acc[i][j];
        }
    }
}

// ---------------- generic 128x128 GEMM (kv_b, o_w) ----------------
__global__ __launch_bounds__(256, 2) void sgemm_nt_db(
    const float* __restrict__ A, int lda,
    const float* __restrict__ B, int ldb,
    float* __restrict__ C, int ldc,
    int M, int N, int K, float alpha)
{
    __shared__ float As[2][8][128];
    __shared__ float Bs[2][8][128];
    gemm_body_128(A, lda, B, ldb, C, ldc, M, N, K, alpha,
                  blockIdx.y * 128, blockIdx.x * 128, As, Bs);
}

// ---------------- fused A=hidden (K=2048) GEMM: qr | ckv | ik | iw ----------------
__global__ __launch_bounds__(256, 2) void fused_hidden_gemm(
    const float* __restrict__ A,
    const float* __restrict__ Bqr,  const float* __restrict__ Bckv,
    const float* __restrict__ Bik,  const float* __restrict__ Biw)
{
    __shared__ float As[2][8][128];
    __shared__ float Bs[2][8][128];
    int bx = blockIdx.x;
    const float* B; float* C; int N, ldc, n0; float alpha = 1.f;
    if (bx < 12)      { B = Bqr;  C = g_qr;    N = QR_;   ldc = QR_;   n0 = bx * 128; }
    else if (bx < 17) { B = Bckv; C = g_ckv;   N = CKVW_; ldc = CKVW_; n0 = (bx - 12) * 128; }
    else if (bx == 17){ B = Bik;  C = g_ikpre; N = ID_;   ldc = ID_;   n0 = 0; }
    else              { B = Biw;  C = g_iw;    N = IH_;   ldc = IH_;   n0 = 0; alpha = 0.25f; }
    gemm_body_128(A, HID_, B, HID_, C, ldc, S_, N, HID_, alpha,
                  blockIdx.y * 128, n0, As, Bs);
}

// ---------------- fused A=qr (K=1536) GEMM: q | iq ----------------
__global__ __launch_bounds__(256, 2) void fused_qr_gemm(
    const float* __restrict__ Bq, const float* __restrict__ Biq)
{
    __shared__ float As[2][8][128];
    __shared__ float Bs[2][8][128];
    int bx = blockIdx.x;
    const float* B; float* C; int N, n0;
    if (bx < 24) { B = Bq;  C = g_q;  N = H_ * 192;  n0 = bx * 128; }
    else         { B = Biq; C = g_iq; N = IH_ * ID_; n0 = (bx - 24) * 128; }
    gemm_body_128(g_qr, QR_, B, QR_, C, N, S_, N, QR_, 1.f,
                  blockIdx.y * 128, n0, As, Bs);
}

// ---------------- rmsnorm (in-place) ----------------
__global__ __launch_bounds__(256) void rmsnorm_kernel(float* __restrict__ x,
                                                      const float* __restrict__ w, int n) {
    __shared__ float sh[33];
    int row = blockIdx.x, t = threadIdx.x;
    float* p = x + (size_t)row * n;
    int cnt = n / 256;
    float local[8];
    float ss = 0.f;
    for (int i = 0; i < cnt; i++) { float v = p[t + i * 256]; local[i] = v; ss += v * v; }
    float total = blockReduceSum(ss, sh);
    float scale = rsqrtf(total / (float)n + EPS_);
    for (int i = 0; i < cnt; i++) p[t + i * 256] = local[i] * scale * w[t + i * 256];
}

// ---------------- ckv split ----------------
__global__ __launch_bounds__(256) void ckv_split_kernel(const float* __restrict__ w) {
    __shared__ float sh[33];
    int s = blockIdx.x, t = threadIdx.x;
    const float* p = g_ckv + (size_t)s * CKVW_;
    float v0 = p[t], v1 = p[256 + t];
    float total = blockReduceSum(v0 * v0 + v1 * v1, sh);
    float scale = rsqrtf(total / (float)KVR_ + EPS_);
    g_ckvn[(size_t)s * KVR_ + t] = v0 * scale * w[t];
    g_ckvn[(size_t)s * KVR_ + 256 + t] = v1 * scale * w[256 + t];
    if (t < 32) {
        float x1 = p[KVR_ + t], x2 = p[KVR_ + 32 + t];
        float c = g_cosb[s * 32 + t], sn = g_sinb[s * 32 + t];
        g_kpe[s * ROPE_ + t] = x1 * c - x2 * sn;
        g_kpe[s * ROPE_ + 32 + t] = x2 * c + x1 * sn;
    }
}

// ---------------- layernorm + rope for ik ----------------
__global__ __launch_bounds__(128) void ik_ln_rope_kernel(const float* __restrict__ xin,
                                                         const float* __restrict__ w,
                                                         const float* __restrict__ b) {
    __shared__ float sh[33];
    __shared__ float sn_[128];
    int s = blockIdx.x, t = threadIdx.x;
    float x = xin[(size_t)s * ID_ + t];
    float mean = blockReduceSum(x, sh) / (float)ID_;
    float var = blockReduceSum(x * x, sh) / (float)ID_ - mean * mean;
    float nv = (x - mean) * rsqrtf(var + EPS_) * w[t] + b[t];
    sn_[t] = nv;
    __syncthreads();
    float out;
    if (t < 32) {
        float c = g_cosb[s * 32 + t], snv = g_sinb[s * 32 + t];
        out = sn_[t] * c - sn_[t + 32] * snv;
    } else if (t < 64) {
        float c = g_cosb[s * 32 + (t - 32)], snv = g_sinb[s * 32 + (t - 32)];
        out = sn_[t] * c + sn_[t - 32] * snv;
    } else {
        out = nv;
    }
    g_ik[(size_t)s * ID_ + t] = out;
}

// ---------------- generic in-place rope over heads ----------------
__global__ void rope_kernel(float* __restrict__ base, int rowStride, int headStride) {
    int s = blockIdx.x;
    int h = threadIdx.y, d = threadIdx.x;
    float* p = base + (size_t)s * rowStride + h * headStride;
    float c = g_cosb[s * 32 + d], sn = g_sinb[s * 32 + d];
    float x1 = p[d], x2 = p[d + 32];
    p[d] = x1 * c - x2 * sn;
    p[d + 32] = x2 * c + x1 * sn;
}

// ============ fused indexer (scalar FFMA) + causal skip ============
__global__ __launch_bounds__(256, 2) void idx_scores_kernel() {
    int m0 = blockIdx.y * 128, n0 = blockIdx.x * 64;
    int t = threadIdx.x;
    int tx = t & 15, ty = t >> 4;
    const float NINF = __int_as_float(0xff800000);

    if (m0 + 128 <= TOPK_) return;                 // rows never read by topk
    if (n0 >= m0 + 128) {                          // fully above diagonal
        #pragma unroll
        for (int i = 0; i < 8; i++) {
            int gm = m0 + ty * 8 + i;
            #pragma unroll
            for (int j = 0; j < 4; j++)
                g_scores[(size_t)gm * S_ + n0 + tx * 4 + j] = NINF;
        }
        return;
    }

    __shared__ float Bs[128][64];          // ik slab [k][n]
    __shared__ float As[2][8][128];        // iq chunk, double buffered
    int a_m = t >> 1, a_k = (t & 1) * 4;

    for (int i = t; i < 64 * 32; i += 256) {
        int nl = i >> 5, k4 = (i & 31) * 4;
        float4 v = *reinterpret_cast<const float4*>(&g_ik[(size_t)(n0 + nl) * ID_ + k4]);
        Bs[k4+0][nl] = v.x; Bs[k4+1][nl] = v.y; Bs[k4+2][nl] = v.z; Bs[k4+3][nl] = v.w;
    }

    float sacc[8][4];
    #pragma unroll
    for (int i = 0; i < 8; i++)
        #pragma unroll
        for (int j = 0; j < 4; j++) sacc[i][j] = 0.f;
    __syncthreads();

    const size_t lda = IH_ * ID_;
    for (int h = 0; h < IH_; h++) {
        const float* A = g_iq + (size_t)h * ID_ + (size_t)(m0 + a_m) * lda;
        {
            float4 v = *reinterpret_cast<const float4*>(&A[a_k]);
            As[0][a_k+0][a_m]=v.x; As[0][a_k+1][a_m]=v.y; As[0][a_k+2][a_m]=v.z; As[0][a_k+3][a_m]=v.w;
        }
        __syncthreads();
        float tacc[8][4];
        #pragma unroll
        for (int i = 0; i < 8; i++)
            #pragma unroll
            for (int j = 0; j < 4; j++) tacc[i][j] = 0.f;
        int buf = 0;
        for (int k0 = 0; k0 < 128; k0 += 8) {
            float4 v;
            bool nxt = (k0 + 8) < 128;
            if (nxt) v = *reinterpret_cast<const float4*>(&A[k0 + 8 + a_k]);
            #pragma unroll
            for (int k = 0; k < 8; k++) {
                float4 a0 = *reinterpret_cast<const float4*>(&As[buf][k][ty * 8]);
                float4 a1 = *reinterpret_cast<const float4*>(&As[buf][k][ty * 8 + 4]);
                float4 b0 = *reinterpret_cast<const float4*>(&Bs[k0 + k][tx * 4]);
                float ra[8] = {a0.x,a0.y,a0.z,a0.w,a1.x,a1.y,a1.z,a1.w};
                float rb[4] = {b0.x,b0.y,b0.z,b0.w};
                #pragma unroll
                for (int i = 0; i < 8; i++)
                    #pragma unroll
                    for (int j = 0; j < 4; j++) tacc[i][j] += ra[i] * rb[j];
            }
            if (nxt) {
                int nb = buf ^ 1;
                As[nb][a_k+0][a_m]=v.x; As[nb][a_k+1][a_m]=v.y; As[nb][a_k+2][a_m]=v.z; As[nb][a_k+3][a_m]=v.w;
                __syncthreads();
                buf = nb;
            }
        }
        __syncthreads();   // protect As[0] for next head vs. last-chunk readers
        #pragma unroll
        for (int i = 0; i < 8; i++) {
            float w = g_iw[(size_t)(m0 + ty * 8 + i) * IH_ + h];   // warp-broadcast, L1-hot
            #pragma unroll
            for (int j = 0; j < 4; j++) {
                float add = __fmul_rn(w, fmaxf(tacc[i][j], 0.f));  // separate roundings
                sacc[i][j] = __fadd_rn(sacc[i][j], add);           // (validated semantics)
            }
        }
    }
    #pragma unroll
    for (int i = 0; i < 8; i++) {
        int gm = m0 + ty * 8 + i;
        #pragma unroll
        for (int j = 0; j < 4; j++) {
            int gn = n0 + tx * 4 + j;
            g_scores[(size_t)gm * S_ + gn] = (gn <= gm) ? sacc[i][j] : NINF;
        }
    }
}

// ---------------- top-k (stable, jax tie semantics) ----------------
__device__ __forceinline__ unsigned fkey(float f) {
    unsigned u = __float_as_uint(f);
    return u ^ ((u >> 31) ? 0xFFFFFFFFu : 0x80000000u);
}

__global__ __launch_bounds__(256) void topk_kernel() {
    int q = blockIdx.x, t = threadIdx.x;
    const float* sc = g_scores + (size_t)q * S_;
    if (q < TOPK_) {
        for (int i = t; i <= q; i += 256) g_sel[(size_t)q * TOPK_ + i] = i;
        if (t == 0) g_nsel[q] = q + 1;
        return;
    }
    __shared__ unsigned hist[256];
    __shared__ unsigned s_pref, s_r;
    __shared__ int s_gt[257], s_eq[257];

    unsigned pref = 0, r = TOPK_;
    #pragma unroll
    for (int p = 3; p >= 0; p--) {
        hist[t] = 0;
        __syncthreads();
        for (int i = t; i < S_; i += 256) {
            unsigned u = fkey(sc[i]);
            bool ok = (p == 3) || ((u >> ((p + 1) * 8)) == pref);
            if (ok) atomicAdd(&hist[(u >> (p * 8)) & 255], 1u);
        }
        __syncthreads();
        if (t == 0) {
            unsigned run = 0;
            int b = 255;
            for (; b >= 0; b--) {
                unsigned c = hist[b];
                if (run + c >= r) break;
                run += c;
            }
            s_pref = (pref << 8) | (unsigned)b;
            s_r = r - run;
        }
        __syncthreads();
        pref = s_pref; r = s_r;
        __syncthreads();
    }
    unsigned T = pref;
    int need_eq = (int)r;

    int i0 = t * 8;
    unsigned keys[8];
    int cg = 0, ce = 0;
    #pragma unroll
    for (int k = 0; k < 8; k++) {
        unsigned u = fkey(sc[i0 + k]);
        keys[k] = u;
        cg += (u > T);
        ce += (u == T);
    }
    s_gt[t] = cg; s_eq[t] = ce;
    __syncthreads();
    if (t == 0) {
        int rg = 0, re = 0;
        for (int i = 0; i < 256; i++) {
            int a = s_gt[i]; s_gt[i] = rg; rg += a;
            int b2 = s_eq[i]; s_eq[i] = re; re += b2;
        }
        s_gt[256] = rg;
    }
    __syncthreads();
    int gpos = s_gt[t], epos = s_eq[t], total_gt = s_gt[256];
    int* out = g_sel + (size_t)q * TOPK_;
    #pragma unroll
    for (int k = 0; k < 8; k++) {
        unsigned u = keys[k];
        if (u > T) out[gpos++] = i0 + k;
        else if (u == T) {
            if (epos < need_eq) out[total_gt + epos] = i0 + k;
            epos++;
        }
    }
    if (t == 0) g_nsel[q] = TOPK_;
}

// ============ sparse attention: one block per query, 16 warps = 16 heads ============
// s_idx and kpe staged in SMEM once per block (kills 15/16 of kpe L2 traffic);
// per-warp softmax (no block barriers in the hot loops). All downstream of top-k.
#define ACHUNK_ 32
__global__ __launch_bounds__(512) void sparse_attn_kernel() {
    const float SCALE = 0.07216878364870322f;
    int qi = blockIdx.x;
    int t = threadIdx.x, h = t >> 5, lane = t & 31;
    __shared__ int   s_idx[TOPK_];                 // 2 KB
    __shared__ float s_p[H_][TOPK_];               // 32 KB
    __shared__ float kpe_s[ACHUNK_][ROPE_];        // 8 KB

    int n = g_nsel[qi];
    const float* qptr = g_q + (size_t)qi * (H_ * 192) + h * 192;
    float4 qn = reinterpret_cast<const float4*>(qptr)[lane];
    float2 qp = reinterpret_cast<const float2*>(qptr + 128)[lane];

    for (int i = t; i < n; i += 512) s_idx[i] = g_sel[(size_t)qi * TOPK_ + i];
    __syncthreads();

    for (int c0 = 0; c0 < n; c0 += ACHUNK_) {
        int cnt = min(ACHUNK_, n - c0);
        // cooperative kpe stage: cnt rows x 32 float2
        for (int u = t; u < cnt * 32; u += 512) {
            int row = u >> 5, col = u & 31;
            reinterpret_cast<float2*>(&kpe_s[row][0])[col] =
                reinterpret_cast<const float2*>(&g_kpe[(size_t)s_idx[c0 + row] * ROPE_])[col];
        }
        __syncthreads();
        for (int jj = 0; jj < cnt; jj++) {
            int j = c0 + jj;
            int kidx = s_idx[j];
            float4 b = reinterpret_cast<const float4*>(g_kv + (size_t)kidx * (H_ * 256) + h * 256)[lane];
            float d = qn.x * b.x + qn.y * b.y + qn.z * b.z + qn.w * b.w;
            float2 bp = reinterpret_cast<const float2*>(&kpe_s[jj][0])[lane];
            d += qp.x * bp.x + qp.y * bp.y;
            #pragma unroll
            for (int o = 16; o; o >>= 1) d += __shfl_down_sync(0xffffffffu, d, o);
            if (lane == 0) s_p[h][j] = d * SCALE;
        }
        __syncthreads();
    }

    // per-warp softmax over s_p[h][0..n)
    float m = -3.4e38f;
    for (int i = lane; i < n; i += 32) m = fmaxf(m, s_p[h][i]);
    #pragma unroll
    for (int o = 16; o; o >>= 1) m = fmaxf(m, __shfl_xor_sync(0xffffffffu, m, o));
    float sum = 0.f;
    for (int i = lane; i < n; i += 32) {
        float e = __expf(s_p[h][i] - m);
        s_p[h][i] = e;
        sum += e;
    }
    #pragma unroll
    for (int o = 16; o; o >>= 1) sum += __shfl_xor_sync(0xffffffffu, sum, o);
    float inv = 1.0f / sum;
    __syncwarp();

    // V accumulation: warp-sequential over keys, lane-parallel over 4 V components
    float4 acc = make_float4(0.f, 0.f, 0.f, 0.f);
    for (int j = 0; j < n; j++) {
        float p = s_p[h][j];
        float4 v = reinterpret_cast<const float4*>(g_kv + (size_t)s_idx[j] * (H_ * 256) + h * 256 + 128)[lane];
        acc.x += p * v.x; acc.y += p * v.y; acc.z += p * v.z; acc.w += p * v.w;
    }
    float4 r = make_float4(acc.x * inv, acc.y * inv, acc.z * inv, acc.w * inv);
    reinterpret_cast<float4*>(g_attn + (size_t)qi * (H_ * VDIM_) + h * VDIM_)[lane] = r;
}

// ---------------- launch ----------------
extern "C" void kernel_launch(void* const* d_in, const int* in_sizes, int n_in,
                              void* d_out, int out_size) {
    (void)in_sizes; (void)n_in; (void)out_size;
    const float* hidden      = (const float*)d_in[0];
    const float* q_a_w       = (const float*)d_in[1];
    const float* q_a_ln_w    = (const float*)d_in[2];
    const float* q_b_w       = (const float*)d_in[3];
    const float* kv_a_w      = (const float*)d_in[4];
    const float* kv_a_ln_w   = (const float*)d_in[5];
    const float* kv_b_w      = (const float*)d_in[6];
    const float* o_w         = (const float*)d_in[7];
    const float* idx_wq_b_w  = (const float*)d_in[8];
    const float* idx_wk_w    = (const float*)d_in[9];
    const float* idx_kn_w    = (const float*)d_in[10];
    const float* idx_kn_b    = (const float*)d_in[11];
    const float* idx_wproj_w = (const float*)d_in[12];
    float* out = (float*)d_out;

    float *p_qr, *p_q, *p_ckvn, *p_kv, *p_iq, *p_ikpre, *p_attn;
    cudaGetSymbolAddress((void**)&p_qr,    g_qr);
    cudaGetSymbolAddress((void**)&p_q,     g_q);
    cudaGetSymbolAddress((void**)&p_ckvn,  g_ckvn);
    cudaGetSymbolAddress((void**)&p_kv,    g_kv);
    cudaGetSymbolAddress((void**)&p_iq,    g_iq);
    cudaGetSymbolAddress((void**)&p_ikpre, g_ikpre);
    cudaGetSymbolAddress((void**)&p_attn,  g_attn);

    dim3 tb(256);

    cossin_kernel<<<S_, 32>>>();

    // qr | ckv | ik | iw — one fused wave over A=hidden (K=2048)
    fused_hidden_gemm<<<dim3(19, S_ / 128), tb>>>(hidden, q_a_w, kv_a_w, idx_wk_w, idx_wproj_w);
    rmsnorm_kernel<<<S_, 256>>>(p_qr, q_a_ln_w, QR_);
    ckv_split_kernel<<<S_, 256>>>(kv_a_ln_w);
    ik_ln_rope_kernel<<<S_, 128>>>(p_ikpre, idx_kn_w, idx_kn_b);

    // q | iq — one fused launch over A=qr (K=1536)
    fused_qr_gemm<<<dim3(40, S_ / 128), tb>>>(q_b_w, idx_wq_b_w);

    // kv = ckvn @ kv_b_w^T   [S, 4096]
    sgemm_nt_db<<<dim3((H_ * 256) / 128, S_ / 128), tb>>>(p_ckvn, KVR_, kv_b_w, KVR_, p_kv, H_ * 256, S_, H_ * 256, KVR_, 1.f);

    // rope q_pe and iq
    rope_kernel<<<S_, dim3(32, H_)>>>(p_q + NOPE_, H_ * 192, 192);
    rope_kernel<<<S_, dim3(32, IH_)>>>(p_iq, IH_ * ID_, ID_);

    // fused indexer scores (causal skip)
    idx_scores_kernel<<<dim3(S_ / 64, S_ / 128), tb>>>();

    topk_kernel<<<S_, 256>>>();

    sparse_attn_kernel<<<S_, 512>>>();

    // out = attn @ o_w^T   [S, 2048]
    sgemm_nt_db<<<dim3(HID_ / 128, S_ / 128), tb>>>(p_attn, H_ * VDIM_, o_w, H_ * VDIM_, out, HID_, S_, HID_, H_ * VDIM_, 1.f);
}

// round 10
// speedup vs baseline: 1.1265x; 1.1265x over previous
#include <cuda_runtime.h>
#include <math.h>

#define S_    2048
#define HID_  2048
#define H_    16
#define NOPE_ 128
#define ROPE_ 64
#define VDIM_ 128
#define QR_   1536
#define KVR_  512
#define IH_   16
#define ID_   128
#define TOPK_ 512
#define EPS_  1e-6f
#define CKVX_ 640          // extended ckv row: 512 ckv | 64 kpe-src | 16 iw | 48 pad

typedef unsigned long long u64;

// ---------------- packed f32x2 helpers (bit-identical to two scalar FFMAs) ----------------
__device__ __forceinline__ void ffma2(u64 &d, u64 a, u64 b) {
    asm("fma.rn.f32x2 %0, %1, %2, %0;" : "+l"(d) : "l"(a), "l"(b));
}
__device__ __forceinline__ u64 pack2(float lo, float hi) {
    u64 r; asm("mov.b64 %0, {%1, %2};" : "=l"(r) : "f"(lo), "f"(hi)); return r;
}
__device__ __forceinline__ float2 unpack2(u64 v) {
    float2 r; asm("mov.b64 {%0, %1}, %2;" : "=f"(r.x), "=f"(r.y) : "l"(v)); return r;
}

// ---------------- scratch ----------------
__device__ float g_qr    [S_*QR_];
__device__ float g_q     [S_*H_*(NOPE_+ROPE_)];
__device__ float g_ckvx  [S_*CKVX_];
__device__ float g_bext  [CKVX_*HID_];
__device__ float g_ckvn  [S_*KVR_];
__device__ float g_kpe   [S_*ROPE_];
__device__ float g_kv    [S_*H_*(NOPE_+VDIM_)];
__device__ float g_iq    [S_*IH_*ID_];
__device__ float g_ikpre [S_*ID_];
__device__ float g_ik    [S_*ID_];
__device__ float g_scores[S_*S_];
__device__ int   g_sel   [S_*TOPK_];
__device__ int   g_nsel  [S_];
__device__ float g_attn  [S_*H_*VDIM_];
__device__ float g_cosb  [S_*32];
__device__ float g_sinb  [S_*32];

// ---------------- helpers ----------------
__device__ __forceinline__ float blockReduceSum(float v, float* sh) {
    int lane = threadIdx.x & 31, w = threadIdx.x >> 5;
    #pragma unroll
    for (int o = 16; o; o >>= 1) v += __shfl_xor_sync(0xffffffffu, v, o);
    if (lane == 0) sh[w] = v;
    __syncthreads();
    int nw = (blockDim.x + 31) >> 5;
    float r = (threadIdx.x < nw) ? sh[threadIdx.x] : 0.f;
    if (w == 0) {
        #pragma unroll
        for (int o = 16; o; o >>= 1) r += __shfl_xor_sync(0xffffffffu, r, o);
        if (lane == 0) sh[0] = r;
    }
    __syncthreads();
    float out = sh[0];
    __syncthreads();
    return out;
}

// ---------------- cos/sin (bit-exact numpy float32 path) ----------------
__global__ void cossin_kernel() {
    int s = blockIdx.x, d = threadIdx.x;
    float e = (float)(2 * d) / 64.0f;
    float pf = (float)pow(10000.0, (double)e);
    float inv = __fdiv_rn(1.0f, pf);
    float f = __fmul_rn((float)s, inv);
    g_cosb[s * 32 + d] = (float)cos((double)f);
    g_sinb[s * 32 + d] = (float)sin((double)f);
}

// ---------------- build extended B slab: kv_a_w | 0.25*idx_wproj_w | zeros ----------------
// 0.25 is a power of two -> per-product scaling is bitwise-exact vs epilogue alpha.
__global__ __launch_bounds__(256) void build_bext_kernel(
    const float* __restrict__ kv_a_w, const float* __restrict__ idx_wproj_w)
{
    size_t idx = (size_t)blockIdx.x * 256 + threadIdx.x;   // over CKVX_*HID_/4 float4s
    size_t row = idx / (HID_ / 4), c4 = idx % (HID_ / 4);
    float4 v;
    if (row < 576) {
        v = reinterpret_cast<const float4*>(kv_a_w)[row * (HID_ / 4) + c4];
    } else if (row < 592) {
        v = reinterpret_cast<const float4*>(idx_wproj_w)[(row - 576) * (HID_ / 4) + c4];
        v.x *= 0.25f; v.y *= 0.25f; v.z *= 0.25f; v.w *= 0.25f;
    } else {
        v = make_float4(0.f, 0.f, 0.f, 0.f);
    }
    reinterpret_cast<float4*>(g_bext)[idx] = v;
}

// ============ shared GEMM body: 128x128 tile, conflict-free quadrant microtile, FFMA2 ============
__device__ __forceinline__ void gemm_body_128(
    const float* __restrict__ A, int lda,
    const float* __restrict__ B, int ldb,
    float* __restrict__ C, int ldc,
    int M, int N, int K, float alpha,
    int m0, int n0,
    float (*As)[8][128], float (*Bs)[8][128])
{
    int t = threadIdx.x;
    int tx = t & 15, ty = t >> 4;
    int a_m = t >> 1, a_k = (t & 1) * 4;
    int gmA = m0 + a_m, gnB = n0 + a_m;
    u64 acc[8][4];
    #pragma unroll
    for (int i = 0; i < 8; i++)
        #pragma unroll
        for (int j = 0; j < 4; j++) acc[i][j] = 0ull;

    float4 va = make_float4(0.f,0.f,0.f,0.f), vb = va;
    if (gmA < M) va = *reinterpret_cast<const float4*>(&A[(size_t)gmA * lda + a_k]);
    if (gnB < N) vb = *reinterpret_cast<const float4*>(&B[(size_t)gnB * ldb + a_k]);
    As[0][a_k+0][a_m]=va.x; As[0][a_k+1][a_m]=va.y; As[0][a_k+2][a_m]=va.z; As[0][a_k+3][a_m]=va.w;
    Bs[0][a_k+0][a_m]=vb.x; Bs[0][a_k+1][a_m]=vb.y; Bs[0][a_k+2][a_m]=vb.z; Bs[0][a_k+3][a_m]=vb.w;
    __syncthreads();
    int buf = 0;
    for (int k0 = 0; k0 < K; k0 += 8) {
        bool nxt = (k0 + 8) < K;
        if (nxt) {
            va = make_float4(0.f,0.f,0.f,0.f); vb = va;
            if (gmA < M) va = *reinterpret_cast<const float4*>(&A[(size_t)gmA * lda + k0 + 8 + a_k]);
            if (gnB < N) vb = *reinterpret_cast<const float4*>(&B[(size_t)gnB * ldb + k0 + 8 + a_k]);
        }
        #pragma unroll
        for (int k = 0; k < 8; k++) {
            float4 a0 = *reinterpret_cast<const float4*>(&As[buf][k][ty * 4]);
            float4 a1 = *reinterpret_cast<const float4*>(&As[buf][k][64 + ty * 4]);
            float4 b0 = *reinterpret_cast<const float4*>(&Bs[buf][k][tx * 4]);
            float4 b1 = *reinterpret_cast<const float4*>(&Bs[buf][k][64 + tx * 4]);
            u64 bb[4] = {pack2(b0.x,b0.y), pack2(b0.z,b0.w), pack2(b1.x,b1.y), pack2(b1.z,b1.w)};
            float ra[8] = {a0.x,a0.y,a0.z,a0.w,a1.x,a1.y,a1.z,a1.w};
            #pragma unroll
            for (int i = 0; i < 8; i++) {
                u64 aa = pack2(ra[i], ra[i]);
                #pragma unroll
                for (int j = 0; j < 4; j++) ffma2(acc[i][j], aa, bb[j]);
            }
        }
        if (nxt) {
            int nb = buf ^ 1;
            As[nb][a_k+0][a_m]=va.x; As[nb][a_k+1][a_m]=va.y; As[nb][a_k+2][a_m]=va.z; As[nb][a_k+3][a_m]=va.w;
            Bs[nb][a_k+0][a_m]=vb.x; Bs[nb][a_k+1][a_m]=vb.y; Bs[nb][a_k+2][a_m]=vb.z; Bs[nb][a_k+3][a_m]=vb.w;
            __syncthreads();
            buf = nb;
        }
    }
    #pragma unroll
    for (int i = 0; i < 8; i++) {
        int gm = m0 + ((i < 4) ? (ty * 4 + i) : (64 + ty * 4 + i - 4));
        if (gm >= M) continue;
        #pragma unroll
        for (int j = 0; j < 4; j++) {
            float2 v = unpack2(acc[i][j]);
            int gn = n0 + ((j < 2) ? (tx * 4 + j * 2) : (64 + tx * 4 + (j - 2) * 2));
            if (gn < N)     C[(size_t)gm * ldc + gn]     = alpha * v.x;
            if (gn + 1 < N) C[(size_t)gm * ldc + gn + 1] = alpha * v.y;
        }
    }
}

// ---------------- generic 128x128 GEMM (o_w) ----------------
__global__ __launch_bounds__(256, 2) void sgemm_nt_db(
    const float* __restrict__ A, int lda,
    const float* __restrict__ B, int ldb,
    float* __restrict__ C, int ldc,
    int M, int N, int K, float alpha)
{
    __shared__ float As[2][8][128];
    __shared__ float Bs[2][8][128];
    gemm_body_128(A, lda, B, ldb, C, ldc, M, N, K, alpha,
                  blockIdx.y * 128, blockIdx.x * 128, As, Bs);
}

// ---------------- fused A=hidden (K=2048) GEMM: qr | ckvx(incl iw) | ik — 288 blocks ----------------
// n-tile map: [0,12) qr(N=1536)  [12,17) ckvx(N=640, Bext)  [17] ik(N=128)
__global__ __launch_bounds__(256, 2) void fused_hidden_gemm(
    const float* __restrict__ A,
    const float* __restrict__ Bqr, const float* __restrict__ Bik)
{
    __shared__ float As[2][8][128];
    __shared__ float Bs[2][8][128];
    int bx = blockIdx.x;
    const float* B; float* C; int N, ldc, n0;
    if (bx < 12)      { B = Bqr;    C = g_qr;    N = QR_;   ldc = QR_;   n0 = bx * 128; }
    else if (bx < 17) { B = g_bext; C = g_ckvx;  N = CKVX_; ldc = CKVX_; n0 = (bx - 12) * 128; }
    else              { B = Bik;    C = g_ikpre; N = ID_;   ldc = ID_;   n0 = 0; }
    gemm_body_128(A, HID_, B, HID_, C, ldc, S_, N, HID_, 1.f,
                  blockIdx.y * 128, n0, As, Bs);
}

// ---------------- fused q | iq | kv_b: backfilled tail ----------------
// bx map: [0,24) q (A=qr,K=1536)  [24,40) iq (A=qr,K=1536)  [40,72) kv_b (A=ckvn,K=512)
__global__ __launch_bounds__(256, 2) void fused_qr_kv_gemm(
    const float* __restrict__ Bq, const float* __restrict__ Biq,
    const float* __restrict__ Bkv)
{
    __shared__ float As[2][8][128];
    __shared__ float Bs[2][8][128];
    int bx = blockIdx.x;
    if (bx < 40) {
        const float* B; float* C; int N, n0;
        if (bx < 24) { B = Bq;  C = g_q;  N = H_ * 192;  n0 = bx * 128; }
        else         { B = Biq; C = g_iq; N = IH_ * ID_; n0 = (bx - 24) * 128; }
        gemm_body_128(g_qr, QR_, B, QR_, C, N, S_, N, QR_, 1.f,
                      blockIdx.y * 128, n0, As, Bs);
    } else {
        gemm_body_128(g_ckvn, KVR_, Bkv, KVR_, g_kv, H_ * 256, S_, H_ * 256, KVR_, 1.f,
                      blockIdx.y * 128, (bx - 40) * 128, As, Bs);
    }
}

// ---------------- rmsnorm (in-place) ----------------
__global__ __launch_bounds__(256) void rmsnorm_kernel(float* __restrict__ x,
                                                      const float* __restrict__ w, int n) {
    __shared__ float sh[33];
    int row = blockIdx.x, t = threadIdx.x;
    float* p = x + (size_t)row * n;
    int cnt = n / 256;
    float local[8];
    float ss = 0.f;
    for (int i = 0; i < cnt; i++) { float v = p[t + i * 256]; local[i] = v; ss += v * v; }
    float total = blockReduceSum(ss, sh);
    float scale = rsqrtf(total / (float)n + EPS_);
    for (int i = 0; i < cnt; i++) p[t + i * 256] = local[i] * scale * w[t + i * 256];
}

// ---------------- ckv split (reads extended row, stride 640) ----------------
__global__ __launch_bounds__(256) void ckv_split_kernel(const float* __restrict__ w) {
    __shared__ float sh[33];
    int s = blockIdx.x, t = threadIdx.x;
    const float* p = g_ckvx + (size_t)s * CKVX_;
    float v0 = p[t], v1 = p[256 + t];
    float total = blockReduceSum(v0 * v0 + v1 * v1, sh);
    float scale = rsqrtf(total / (float)KVR_ + EPS_);
    g_ckvn[(size_t)s * KVR_ + t] = v0 * scale * w[t];
    g_ckvn[(size_t)s * KVR_ + 256 + t] = v1 * scale * w[256 + t];
    if (t < 32) {
        float x1 = p[KVR_ + t], x2 = p[KVR_ + 32 + t];
        float c = g_cosb[s * 32 + t], sn = g_sinb[s * 32 + t];
        g_kpe[s * ROPE_ + t] = x1 * c - x2 * sn;
        g_kpe[s * ROPE_ + 32 + t] = x2 * c + x1 * sn;
    }
}

// ---------------- layernorm + rope for ik ----------------
__global__ __launch_bounds__(128) void ik_ln_rope_kernel(const float* __restrict__ xin,
                                                         const float* __restrict__ w,
                                                         const float* __restrict__ b) {
    __shared__ float sh[33];
    __shared__ float sn_[128];
    int s = blockIdx.x, t = threadIdx.x;
    float x = xin[(size_t)s * ID_ + t];
    float mean = blockReduceSum(x, sh) / (float)ID_;
    float var = blockReduceSum(x * x, sh) / (float)ID_ - mean * mean;
    float nv = (x - mean) * rsqrtf(var + EPS_) * w[t] + b[t];
    sn_[t] = nv;
    __syncthreads();
    float out;
    if (t < 32) {
        float c = g_cosb[s * 32 + t], snv = g_sinb[s * 32 + t];
        out = sn_[t] * c - sn_[t + 32] * snv;
    } else if (t < 64) {
        float c = g_cosb[s * 32 + (t - 32)], snv = g_sinb[s * 32 + (t - 32)];
        out = sn_[t] * c + sn_[t - 32] * snv;
    } else {
        out = nv;
    }
    g_ik[(size_t)s * ID_ + t] = out;
}

// ---------------- generic in-place rope over heads ----------------
__global__ void rope_kernel(float* __restrict__ base, int rowStride, int headStride) {
    int s = blockIdx.x;
    int h = threadIdx.y, d = threadIdx.x;
    float* p = base + (size_t)s * rowStride + h * headStride;
    float c = g_cosb[s * 32 + d], sn = g_sinb[s * 32 + d];
    float x1 = p[d], x2 = p[d + 32];
    p[d] = x1 * c - x2 * sn;
    p[d + 32] = x2 * c + x1 * sn;
}

// ============ fused indexer w/ FFMA2 + causal skip (iw read from g_ckvx col 576+h) ============
__global__ __launch_bounds__(256, 2) void idx_scores_kernel() {
    int m0 = blockIdx.y * 128, n0 = blockIdx.x * 64;
    int t = threadIdx.x;
    int tx = t & 15, ty = t >> 4;
    const float NINF = __int_as_float(0xff800000);

    if (m0 + 128 <= TOPK_) return;                 // rows never read by topk
    if (n0 >= m0 + 128) {                          // fully above diagonal
        #pragma unroll
        for (int i = 0; i < 8; i++) {
            int gm = m0 + ty * 8 + i;
            #pragma unroll
            for (int j = 0; j < 4; j++)
                g_scores[(size_t)gm * S_ + n0 + tx * 4 + j] = NINF;
        }
        return;
    }

    __shared__ float Bs[128][64];          // ik slab [k][n]
    __shared__ float As[2][8][128];        // iq chunk, double buffered
    int a_m = t >> 1, a_k = (t & 1) * 4;

    for (int i = t; i < 64 * 32; i += 256) {
        int nl = i >> 5, k4 = (i & 31) * 4;
        float4 v = *reinterpret_cast<const float4*>(&g_ik[(size_t)(n0 + nl) * ID_ + k4]);
        Bs[k4+0][nl] = v.x; Bs[k4+1][nl] = v.y; Bs[k4+2][nl] = v.z; Bs[k4+3][nl] = v.w;
    }

    float sacc[8][4];
    #pragma unroll
    for (int i = 0; i < 8; i++)
        #pragma unroll
        for (int j = 0; j < 4; j++) sacc[i][j] = 0.f;
    __syncthreads();

    const size_t lda = IH_ * ID_;
    for (int h = 0; h < IH_; h++) {
        const float* A = g_iq + (size_t)h * ID_ + (size_t)(m0 + a_m) * lda;
        {
            float4 v = *reinterpret_cast<const float4*>(&A[a_k]);
            As[0][a_k+0][a_m]=v.x; As[0][a_k+1][a_m]=v.y; As[0][a_k+2][a_m]=v.z; As[0][a_k+3][a_m]=v.w;
        }
        __syncthreads();
        u64 tacc[8][2];
        #pragma unroll
        for (int i = 0; i < 8; i++) { tacc[i][0] = 0ull; tacc[i][1] = 0ull; }
        int buf = 0;
        for (int k0 = 0; k0 < 128; k0 += 8) {
            float4 v;
            bool nxt = (k0 + 8) < 128;
            if (nxt) v = *reinterpret_cast<const float4*>(&A[k0 + 8 + a_k]);
            #pragma unroll
            for (int k = 0; k < 8; k++) {
                float4 a0 = *reinterpret_cast<const float4*>(&As[buf][k][ty * 8]);
                float4 a1 = *reinterpret_cast<const float4*>(&As[buf][k][ty * 8 + 4]);
                float4 b0 = *reinterpret_cast<const float4*>(&Bs[k0 + k][tx * 4]);
                u64 bb[2] = {pack2(b0.x,b0.y), pack2(b0.z,b0.w)};
                float ra[8] = {a0.x,a0.y,a0.z,a0.w,a1.x,a1.y,a1.z,a1.w};
                #pragma unroll
                for (int i = 0; i < 8; i++) {
                    u64 aa = pack2(ra[i], ra[i]);
                    ffma2(tacc[i][0], aa, bb[0]);
                    ffma2(tacc[i][1], aa, bb[1]);
                }
            }
            if (nxt) {
                int nb = buf ^ 1;
                As[nb][a_k+0][a_m]=v.x; As[nb][a_k+1][a_m]=v.y; As[nb][a_k+2][a_m]=v.z; As[nb][a_k+3][a_m]=v.w;
                __syncthreads();
                buf = nb;
            }
        }
        __syncthreads();   // protect As[0] for next head vs. last-chunk readers
        #pragma unroll
        for (int i = 0; i < 8; i++) {
            float w = g_ckvx[(size_t)(m0 + ty * 8 + i) * CKVX_ + 576 + h];  // iw (0.25 baked in, exact)
            float2 t01 = unpack2(tacc[i][0]);
            float2 t23 = unpack2(tacc[i][1]);
            float tv[4] = {t01.x, t01.y, t23.x, t23.y};
            #pragma unroll
            for (int j = 0; j < 4; j++) {
                float add = __fmul_rn(w, fmaxf(tv[j], 0.f));   // separate roundings
                sacc[i][j] = __fadd_rn(sacc[i][j], add);       // (validated semantics)
            }
        }
    }
    #pragma unroll
    for (int i = 0; i < 8; i++) {
        int gm = m0 + ty * 8 + i;
        #pragma unroll
        for (int j = 0; j < 4; j++) {
            int gn = n0 + tx * 4 + j;
            g_scores[(size_t)gm * S_ + gn] = (gn <= gm) ? sacc[i][j] : NINF;
        }
    }
}

// ---------------- top-k (stable, jax tie semantics) ----------------
__device__ __forceinline__ unsigned fkey(float f) {
    unsigned u = __float_as_uint(f);
    return u ^ ((u >> 31) ? 0xFFFFFFFFu : 0x80000000u);
}

__global__ __launch_bounds__(256) void topk_kernel() {
    int q = blockIdx.x, t = threadIdx.x;
    const float* sc = g_scores + (size_t)q * S_;
    if (q < TOPK_) {
        for (int i = t; i <= q; i += 256) g_sel[(size_t)q * TOPK_ + i] = i;
        if (t == 0) g_nsel[q] = q + 1;
        return;
    }
    __shared__ unsigned hist[256];
    __shared__ unsigned s_pref, s_r;
    __shared__ int s_gt[257], s_eq[257];

    unsigned pref = 0, r = TOPK_;
    #pragma unroll
    for (int p = 3; p >= 0; p--) {
        hist[t] = 0;
        __syncthreads();
        for (int i = t; i < S_; i += 256) {
            unsigned u = fkey(sc[i]);
            bool ok = (p == 3) || ((u >> ((p + 1) * 8)) == pref);
            if (ok) atomicAdd(&hist[(u >> (p * 8)) & 255], 1u);
        }
        __syncthreads();
        if (t == 0) {
            unsigned run = 0;
            int b = 255;
            for (; b >= 0; b--) {
                unsigned c = hist[b];
                if (run + c >= r) break;
                run += c;
            }
            s_pref = (pref << 8) | (unsigned)b;
            s_r = r - run;
        }
        __syncthreads();
        pref = s_pref; r = s_r;
        __syncthreads();
    }
    unsigned T = pref;
    int need_eq = (int)r;

    int i0 = t * 8;
    unsigned keys[8];
    int cg = 0, ce = 0;
    #pragma unroll
    for (int k = 0; k < 8; k++) {
        unsigned u = fkey(sc[i0 + k]);
        keys[k] = u;
        cg += (u > T);
        ce += (u == T);
    }
    s_gt[t] = cg; s_eq[t] = ce;
    __syncthreads();
    if (t == 0) {
        int rg = 0, re = 0;
        for (int i = 0; i < 256; i++) {
            int a = s_gt[i]; s_gt[i] = rg; rg += a;
            int b2 = s_eq[i]; s_eq[i] = re; re += b2;
        }
        s_gt[256] = rg;
    }
    __syncthreads();
    int gpos = s_gt[t], epos = s_eq[t], total_gt = s_gt[256];
    int* out = g_sel + (size_t)q * TOPK_;
    #pragma unroll
    for (int k = 0; k < 8; k++) {
        unsigned u = keys[k];
        if (u > T) out[gpos++] = i0 + k;
        else if (u == T) {
            if (epos < need_eq) out[total_gt + epos] = i0 + k;
            epos++;
        }
    }
    if (t == 0) g_nsel[q] = TOPK_;
}

// ---------------- sparse attention (round-8 validated version) ----------------
__global__ __launch_bounds__(128) void sparse_attn_kernel() {
    const float SCALE = 0.07216878364870322f;
    int qi = blockIdx.x, h = blockIdx.y;
    int t = threadIdx.x, w = t >> 5, lane = t & 31;
    __shared__ float qv[192];
    __shared__ float s_p[TOPK_];
    __shared__ int s_idx[TOPK_];
    __shared__ float s_red[4];
    __shared__ float s_out[4][128];

    int n = g_nsel[qi];
    const float* qptr = g_q + (size_t)qi * (H_ * 192) + h * 192;
    for (int i = t; i < 192; i += 128) qv[i] = qptr[i];
    for (int i = t; i < n; i += 128) s_idx[i] = g_sel[(size_t)qi * TOPK_ + i];
    __syncthreads();

    for (int j = w; j < n; j += 4) {
        int kidx = s_idx[j];
        const float4* kn = reinterpret_cast<const float4*>(g_kv + (size_t)kidx * (H_ * 256) + h * 256);
        float4 a = reinterpret_cast<const float4*>(qv)[lane];
        float4 b = kn[lane];
        float d = a.x * b.x + a.y * b.y + a.z * b.z + a.w * b.w;
        const float2* kp = reinterpret_cast<const float2*>(g_kpe + (size_t)kidx * ROPE_);
        float2 ap = reinterpret_cast<const float2*>(qv + 128)[lane];
        float2 bp = kp[lane];
        d += ap.x * bp.x + ap.y * bp.y;
        #pragma unroll
        for (int o = 16; o; o >>= 1) d += __shfl_down_sync(0xffffffffu, d, o);
        if (lane == 0) s_p[j] = d * SCALE;
    }
    __syncthreads();

    float m = -3.4e38f;
    for (int i = t; i < n; i += 128) m = fmaxf(m, s_p[i]);
    #pragma unroll
    for (int o = 16; o; o >>= 1) m = fmaxf(m, __shfl_xor_sync(0xffffffffu, m, o));
    if (lane == 0) s_red[w] = m;
    __syncthreads();
    m = fmaxf(fmaxf(s_red[0], s_red[1]), fmaxf(s_red[2], s_red[3]));
    __syncthreads();

    float sum = 0.f;
    for (int i = t; i < n; i += 128) {
        float e = __expf(s_p[i] - m);
        s_p[i] = e;
        sum += e;
    }
    #pragma unroll
    for (int o = 16; o; o >>= 1) sum += __shfl_xor_sync(0xffffffffu, sum, o);
    __syncthreads();
    if (lane == 0) s_red[w] = sum;
    __syncthreads();
    sum = s_red[0] + s_red[1] + s_red[2] + s_red[3];
    float inv = 1.0f / sum;

    float4 acc = make_float4(0.f, 0.f, 0.f, 0.f);
    for (int j = w; j < n; j += 4) {
        float p = s_p[j];
        int kidx = s_idx[j];
        float4 v = reinterpret_cast<const float4*>(g_kv + (size_t)kidx * (H_ * 256) + h * 256 + 128)[lane];
        acc.x += p * v.x; acc.y += p * v.y; acc.z += p * v.z; acc.w += p * v.w;
    }
    reinterpret_cast<float4*>(&s_out[w][0])[lane] = acc;
    __syncthreads();
    float o = (s_out[0][t] + s_out[1][t] + s_out[2][t] + s_out[3][t]) * inv;
    g_attn[(size_t)qi * (H_ * VDIM_) + h * VDIM_ + t] = o;
}

// ---------------- launch ----------------
extern "C" void kernel_launch(void* const* d_in, const int* in_sizes, int n_in,
                              void* d_out, int out_size) {
    (void)in_sizes; (void)n_in; (void)out_size;
    const float* hidden      = (const float*)d_in[0];
    const float* q_a_w       = (const float*)d_in[1];
    const float* q_a_ln_w    = (const float*)d_in[2];
    const float* q_b_w       = (const float*)d_in[3];
    const float* kv_a_w      = (const float*)d_in[4];
    const float* kv_a_ln_w   = (const float*)d_in[5];
    const float* kv_b_w      = (const float*)d_in[6];
    const float* o_w         = (const float*)d_in[7];
    const float* idx_wq_b_w  = (const float*)d_in[8];
    const float* idx_wk_w    = (const float*)d_in[9];
    const float* idx_kn_w    = (const float*)d_in[10];
    const float* idx_kn_b    = (const float*)d_in[11];
    const float* idx_wproj_w = (const float*)d_in[12];
    float* out = (float*)d_out;

    float *p_qr, *p_q, *p_iq, *p_ikpre, *p_attn;
    cudaGetSymbolAddress((void**)&p_qr,    g_qr);
    cudaGetSymbolAddress((void**)&p_q,     g_q);
    cudaGetSymbolAddress((void**)&p_iq,    g_iq);
    cudaGetSymbolAddress((void**)&p_ikpre, g_ikpre);
    cudaGetSymbolAddress((void**)&p_attn,  g_attn);

    dim3 tb(256);

    cossin_kernel<<<S_, 32>>>();
    build_bext_kernel<<<(CKVX_ * HID_ / 4 + 255) / 256, 256>>>(kv_a_w, idx_wproj_w);

    // qr | ckvx(incl 0.25*iw) | ik — 288 blocks, single wave over A=hidden (K=2048)
    fused_hidden_gemm<<<dim3(18, S_ / 128), tb>>>(hidden, q_a_w, idx_wk_w);
    rmsnorm_kernel<<<S_, 256>>>(p_qr, q_a_ln_w, QR_);
    ckv_split_kernel<<<S_, 256>>>(kv_a_ln_w);
    ik_ln_rope_kernel<<<S_, 128>>>(p_ikpre, idx_kn_w, idx_kn_b);

    // q | iq (K=1536) with kv_b (K=512) backfilling the tail wave
    fused_qr_kv_gemm<<<dim3(72, S_ / 128), tb>>>(q_b_w, idx_wq_b_w, kv_b_w);

    // rope q_pe and iq
    rope_kernel<<<S_, dim3(32, H_)>>>(p_q + NOPE_, H_ * 192, 192);
    rope_kernel<<<S_, dim3(32, IH_)>>>(p_iq, IH_ * ID_, ID_);

    // fused indexer scores (causal skip + FFMA2)
    idx_scores_kernel<<<dim3(S_ / 64, S_ / 128), tb>>>();

    topk_kernel<<<S_, 256>>>();

    sparse_attn_kernel<<<dim3(S_, H_), 128>>>();

    // out = attn @ o_w^T   [S, 2048]
    sgemm_nt_db<<<dim3(HID_ / 128, S_ / 128), tb>>>(p_attn, H_ * VDIM_, o_w, H_ * VDIM_, out, HID_, S_, HID_, H_ * VDIM_, 1.f);
}

// round 11
// speedup vs baseline: 1.2192x; 1.0823x over previous
#include <cuda_runtime.h>
#include <cuda_fp16.h>
#include <math.h>

#define S_    2048
#define HID_  2048
#define H_    16
#define NOPE_ 128
#define ROPE_ 64
#define VDIM_ 128
#define QR_   1536
#define KVR_  512
#define IH_   16
#define ID_   128
#define TOPK_ 512
#define EPS_  1e-6f
#define CKVX_ 640          // extended ckv row: 512 ckv | 64 kpe-src | 16 iw | 48 pad

typedef unsigned long long u64;

// ---------------- packed f32x2 helpers (bit-identical to two scalar FFMAs) ----------------
__device__ __forceinline__ void ffma2(u64 &d, u64 a, u64 b) {
    asm("fma.rn.f32x2 %0, %1, %2, %0;" : "+l"(d) : "l"(a), "l"(b));
}
__device__ __forceinline__ u64 pack2(float lo, float hi) {
    u64 r; asm("mov.b64 %0, {%1, %2};" : "=l"(r) : "f"(lo), "f"(hi)); return r;
}
__device__ __forceinline__ float2 unpack2(u64 v) {
    float2 r; asm("mov.b64 {%0, %1}, %2;" : "=f"(r.x), "=f"(r.y) : "l"(v)); return r;
}

// ---------------- scratch ----------------
__device__ float  g_qr    [S_*QR_];
__device__ float  g_q     [S_*H_*(NOPE_+ROPE_)];
__device__ float  g_ckvx  [S_*CKVX_];
__device__ float  g_bext  [CKVX_*HID_];
__device__ float  g_ckvn  [S_*KVR_];
__device__ float  g_kpe   [S_*ROPE_];
__device__ __half g_kvh   [S_*H_*(NOPE_+VDIM_)];   // fp16 KV — gather path only
__device__ float  g_iq    [S_*IH_*ID_];
__device__ float  g_ikpre [S_*ID_];
__device__ float  g_ik    [S_*ID_];
__device__ float  g_scores[S_*S_];
__device__ int    g_sel   [S_*TOPK_];
__device__ int    g_nsel  [S_];
__device__ float  g_attn  [S_*H_*VDIM_];
__device__ float  g_cosb  [S_*32];
__device__ float  g_sinb  [S_*32];

// ---------------- helpers ----------------
__device__ __forceinline__ float blockReduceSum(float v, float* sh) {
    int lane = threadIdx.x & 31, w = threadIdx.x >> 5;
    #pragma unroll
    for (int o = 16; o; o >>= 1) v += __shfl_xor_sync(0xffffffffu, v, o);
    if (lane == 0) sh[w] = v;
    __syncthreads();
    int nw = (blockDim.x + 31) >> 5;
    float r = (threadIdx.x < nw) ? sh[threadIdx.x] : 0.f;
    if (w == 0) {
        #pragma unroll
        for (int o = 16; o; o >>= 1) r += __shfl_xor_sync(0xffffffffu, r, o);
        if (lane == 0) sh[0] = r;
    }
    __syncthreads();
    float out = sh[0];
    __syncthreads();
    return out;
}

// ---------------- cos/sin (bit-exact numpy float32 path) ----------------
__global__ void cossin_kernel() {
    int s = blockIdx.x, d = threadIdx.x;
    float e = (float)(2 * d) / 64.0f;
    float pf = (float)pow(10000.0, (double)e);
    float inv = __fdiv_rn(1.0f, pf);
    float f = __fmul_rn((float)s, inv);
    g_cosb[s * 32 + d] = (float)cos((double)f);
    g_sinb[s * 32 + d] = (float)sin((double)f);
}

// ---------------- build extended B slab: kv_a_w | 0.25*idx_wproj_w | zeros ----------------
__global__ __launch_bounds__(256) void build_bext_kernel(
    const float* __restrict__ kv_a_w, const float* __restrict__ idx_wproj_w)
{
    size_t idx = (size_t)blockIdx.x * 256 + threadIdx.x;
    size_t row = idx / (HID_ / 4), c4 = idx % (HID_ / 4);
    float4 v;
    if (row < 576) {
        v = reinterpret_cast<const float4*>(kv_a_w)[row * (HID_ / 4) + c4];
    } else if (row < 592) {
        v = reinterpret_cast<const float4*>(idx_wproj_w)[(row - 576) * (HID_ / 4) + c4];
        v.x *= 0.25f; v.y *= 0.25f; v.z *= 0.25f; v.w *= 0.25f;
    } else {
        v = make_float4(0.f, 0.f, 0.f, 0.f);
    }
    reinterpret_cast<float4*>(g_bext)[idx] = v;
}

// ============ shared GEMM body: 128x128 tile, quadrant microtile, FFMA2 ============
// HALF_OUT: epilogue converts each fp32 result to fp16 (round-to-nearest) and stores
// half2 pairs — fp32 accumulation identical; used for the KV gather copy only.
template<bool HALF_OUT>
__device__ __forceinline__ void gemm_body_128(
    const float* __restrict__ A, int lda,
    const float* __restrict__ B, int ldb,
    float* __restrict__ C, int ldc,
    int M, int N, int K, float alpha,
    int m0, int n0,
    float (*As)[8][128], float (*Bs)[8][128])
{
    int t = threadIdx.x;
    int tx = t & 15, ty = t >> 4;
    int a_m = t >> 1, a_k = (t & 1) * 4;
    int gmA = m0 + a_m, gnB = n0 + a_m;
    u64 acc[8][4];
    #pragma unroll
    for (int i = 0; i < 8; i++)
        #pragma unroll
        for (int j = 0; j < 4; j++) acc[i][j] = 0ull;

    float4 va = make_float4(0.f,0.f,0.f,0.f), vb = va;
    if (gmA < M) va = *reinterpret_cast<const float4*>(&A[(size_t)gmA * lda + a_k]);
    if (gnB < N) vb = *reinterpret_cast<const float4*>(&B[(size_t)gnB * ldb + a_k]);
    As[0][a_k+0][a_m]=va.x; As[0][a_k+1][a_m]=va.y; As[0][a_k+2][a_m]=va.z; As[0][a_k+3][a_m]=va.w;
    Bs[0][a_k+0][a_m]=vb.x; Bs[0][a_k+1][a_m]=vb.y; Bs[0][a_k+2][a_m]=vb.z; Bs[0][a_k+3][a_m]=vb.w;
    __syncthreads();
    int buf = 0;
    for (int k0 = 0; k0 < K; k0 += 8) {
        bool nxt = (k0 + 8) < K;
        if (nxt) {
            va = make_float4(0.f,0.f,0.f,0.f); vb = va;
            if (gmA < M) va = *reinterpret_cast<const float4*>(&A[(size_t)gmA * lda + k0 + 8 + a_k]);
            if (gnB < N) vb = *reinterpret_cast<const float4*>(&B[(size_t)gnB * ldb + k0 + 8 + a_k]);
        }
        #pragma unroll
        for (int k = 0; k < 8; k++) {
            float4 a0 = *reinterpret_cast<const float4*>(&As[buf][k][ty * 4]);
            float4 a1 = *reinterpret_cast<const float4*>(&As[buf][k][64 + ty * 4]);
            float4 b0 = *reinterpret_cast<const float4*>(&Bs[buf][k][tx * 4]);
            float4 b1 = *reinterpret_cast<const float4*>(&Bs[buf][k][64 + tx * 4]);
            u64 bb[4] = {pack2(b0.x,b0.y), pack2(b0.z,b0.w), pack2(b1.x,b1.y), pack2(b1.z,b1.w)};
            float ra[8] = {a0.x,a0.y,a0.z,a0.w,a1.x,a1.y,a1.z,a1.w};
            #pragma unroll
            for (int i = 0; i < 8; i++) {
                u64 aa = pack2(ra[i], ra[i]);
                #pragma unroll
                for (int j = 0; j < 4; j++) ffma2(acc[i][j], aa, bb[j]);
            }
        }
        if (nxt) {
            int nb = buf ^ 1;
            As[nb][a_k+0][a_m]=va.x; As[nb][a_k+1][a_m]=va.y; As[nb][a_k+2][a_m]=va.z; As[nb][a_k+3][a_m]=va.w;
            Bs[nb][a_k+0][a_m]=vb.x; Bs[nb][a_k+1][a_m]=vb.y; Bs[nb][a_k+2][a_m]=vb.z; Bs[nb][a_k+3][a_m]=vb.w;
            __syncthreads();
            buf = nb;
        }
    }
    #pragma unroll
    for (int i = 0; i < 8; i++) {
        int gm = m0 + ((i < 4) ? (ty * 4 + i) : (64 + ty * 4 + i - 4));
        if (gm >= M) continue;
        #pragma unroll
        for (int j = 0; j < 4; j++) {
            float2 v = unpack2(acc[i][j]);
            int gn = n0 + ((j < 2) ? (tx * 4 + j * 2) : (64 + tx * 4 + (j - 2) * 2));
            if (HALF_OUT) {
                // full tiles only (kv path: M,N multiples of 128); gn is even
                __half2 hv = __floats2half2_rn(v.x, v.y);
                *reinterpret_cast<__half2*>(reinterpret_cast<__half*>(C) + (size_t)gm * ldc + gn) = hv;
            } else {
                if (gn < N)     C[(size_t)gm * ldc + gn]     = alpha * v.x;
                if (gn + 1 < N) C[(size_t)gm * ldc + gn + 1] = alpha * v.y;
            }
        }
    }
}

// ---------------- generic 128x128 GEMM (o_w) ----------------
__global__ __launch_bounds__(256, 2) void sgemm_nt_db(
    const float* __restrict__ A, int lda,
    const float* __restrict__ B, int ldb,
    float* __restrict__ C, int ldc,
    int M, int N, int K, float alpha)
{
    __shared__ float As[2][8][128];
    __shared__ float Bs[2][8][128];
    gemm_body_128<false>(A, lda, B, ldb, C, ldc, M, N, K, alpha,
                         blockIdx.y * 128, blockIdx.x * 128, As, Bs);
}

// ---------------- fused A=hidden (K=2048): qr | ckvx(incl iw) | ik — 288 blocks ----------------
__global__ __launch_bounds__(256, 2) void fused_hidden_gemm(
    const float* __restrict__ A,
    const float* __restrict__ Bqr, const float* __restrict__ Bik)
{
    __shared__ float As[2][8][128];
    __shared__ float Bs[2][8][128];
    int bx = blockIdx.x;
    const float* B; float* C; int N, ldc, n0;
    if (bx < 12)      { B = Bqr;    C = g_qr;    N = QR_;   ldc = QR_;   n0 = bx * 128; }
    else if (bx < 17) { B = g_bext; C = g_ckvx;  N = CKVX_; ldc = CKVX_; n0 = (bx - 12) * 128; }
    else              { B = Bik;    C = g_ikpre; N = ID_;   ldc = ID_;   n0 = 0; }
    gemm_body_128<false>(A, HID_, B, HID_, C, ldc, S_, N, HID_, 1.f,
                         blockIdx.y * 128, n0, As, Bs);
}

// ---------------- fused q | iq | kv_b(fp16 out): backfilled tail ----------------
__global__ __launch_bounds__(256, 2) void fused_qr_kv_gemm(
    const float* __restrict__ Bq, const float* __restrict__ Biq,
    const float* __restrict__ Bkv)
{
    __shared__ float As[2][8][128];
    __shared__ float Bs[2][8][128];
    int bx = blockIdx.x;
    if (bx < 40) {
        const float* B; float* C; int N, n0;
        if (bx < 24) { B = Bq;  C = g_q;  N = H_ * 192;  n0 = bx * 128; }
        else         { B = Biq; C = g_iq; N = IH_ * ID_; n0 = (bx - 24) * 128; }
        gemm_body_128<false>(g_qr, QR_, B, QR_, C, N, S_, N, QR_, 1.f,
                             blockIdx.y * 128, n0, As, Bs);
    } else {
        gemm_body_128<true>(g_ckvn, KVR_, Bkv, KVR_,
                            reinterpret_cast<float*>(g_kvh), H_ * 256,
                            S_, H_ * 256, KVR_, 1.f,
                            blockIdx.y * 128, (bx - 40) * 128, As, Bs);
    }
}

// ---------------- rmsnorm (in-place) ----------------
__global__ __launch_bounds__(256) void rmsnorm_kernel(float* __restrict__ x,
                                                      const float* __restrict__ w, int n) {
    __shared__ float sh[33];
    int row = blockIdx.x, t = threadIdx.x;
    float* p = x + (size_t)row * n;
    int cnt = n / 256;
    float local[8];
    float ss = 0.f;
    for (int i = 0; i < cnt; i++) { float v = p[t + i * 256]; local[i] = v; ss += v * v; }
    float total = blockReduceSum(ss, sh);
    float scale = rsqrtf(total / (float)n + EPS_);
    for (int i = 0; i < cnt; i++) p[t + i * 256] = local[i] * scale * w[t + i * 256];
}

// ---------------- ckv split (reads extended row, stride 640) ----------------
__global__ __launch_bounds__(256) void ckv_split_kernel(const float* __restrict__ w) {
    __shared__ float sh[33];
    int s = blockIdx.x, t = threadIdx.x;
    const float* p = g_ckvx + (size_t)s * CKVX_;
    float v0 = p[t], v1 = p[256 + t];
    float total = blockReduceSum(v0 * v0 + v1 * v1, sh);
    float scale = rsqrtf(total / (float)KVR_ + EPS_);
    g_ckvn[(size_t)s * KVR_ + t] = v0 * scale * w[t];
    g_ckvn[(size_t)s * KVR_ + 256 + t] = v1 * scale * w[256 + t];
    if (t < 32) {
        float x1 = p[KVR_ + t], x2 = p[KVR_ + 32 + t];
        float c = g_cosb[s * 32 + t], sn = g_sinb[s * 32 + t];
        g_kpe[s * ROPE_ + t] = x1 * c - x2 * sn;
        g_kpe[s * ROPE_ + 32 + t] = x2 * c + x1 * sn;
    }
}

// ---------------- layernorm + rope for ik ----------------
__global__ __launch_bounds__(128) void ik_ln_rope_kernel(const float* __restrict__ xin,
                                                         const float* __restrict__ w,
                                                         const float* __restrict__ b) {
    __shared__ float sh[33];
    __shared__ float sn_[128];
    int s = blockIdx.x, t = threadIdx.x;
    float x = xin[(size_t)s * ID_ + t];
    float mean = blockReduceSum(x, sh) / (float)ID_;
    float var = blockReduceSum(x * x, sh) / (float)ID_ - mean * mean;
    float nv = (x - mean) * rsqrtf(var + EPS_) * w[t] + b[t];
    sn_[t] = nv;
    __syncthreads();
    float out;
    if (t < 32) {
        float c = g_cosb[s * 32 + t], snv = g_sinb[s * 32 + t];
        out = sn_[t] * c - sn_[t + 32] * snv;
    } else if (t < 64) {
        float c = g_cosb[s * 32 + (t - 32)], snv = g_sinb[s * 32 + (t - 32)];
        out = sn_[t] * c + sn_[t - 32] * snv;
    } else {
        out = nv;
    }
    g_ik[(size_t)s * ID_ + t] = out;
}

// ---------------- generic in-place rope over heads ----------------
__global__ void rope_kernel(float* __restrict__ base, int rowStride, int headStride) {
    int s = blockIdx.x;
    int h = threadIdx.y, d = threadIdx.x;
    float* p = base + (size_t)s * rowStride + h * headStride;
    float c = g_cosb[s * 32 + d], sn = g_sinb[s * 32 + d];
    float x1 = p[d], x2 = p[d + 32];
    p[d] = x1 * c - x2 * sn;
    p[d + 32] = x2 * c + x1 * sn;
}

// ============ fused indexer w/ FFMA2 + causal skip (iw from g_ckvx col 576+h) ============
__global__ __launch_bounds__(256, 2) void idx_scores_kernel() {
    int m0 = blockIdx.y * 128, n0 = blockIdx.x * 64;
    int t = threadIdx.x;
    int tx = t & 15, ty = t >> 4;
    const float NINF = __int_as_float(0xff800000);

    if (m0 + 128 <= TOPK_) return;
    if (n0 >= m0 + 128) {
        #pragma unroll
        for (int i = 0; i < 8; i++) {
            int gm = m0 + ty * 8 + i;
            #pragma unroll
            for (int j = 0; j < 4; j++)
                g_scores[(size_t)gm * S_ + n0 + tx * 4 + j] = NINF;
        }
        return;
    }

    __shared__ float Bs[128][64];
    __shared__ float As[2][8][128];
    int a_m = t >> 1, a_k = (t & 1) * 4;

    for (int i = t; i < 64 * 32; i += 256) {
        int nl = i >> 5, k4 = (i & 31) * 4;
        float4 v = *reinterpret_cast<const float4*>(&g_ik[(size_t)(n0 + nl) * ID_ + k4]);
        Bs[k4+0][nl] = v.x; Bs[k4+1][nl] = v.y; Bs[k4+2][nl] = v.z; Bs[k4+3][nl] = v.w;
    }

    float sacc[8][4];
    #pragma unroll
    for (int i = 0; i < 8; i++)
        #pragma unroll
        for (int j = 0; j < 4; j++) sacc[i][j] = 0.f;
    __syncthreads();

    const size_t lda = IH_ * ID_;
    for (int h = 0; h < IH_; h++) {
        const float* A = g_iq + (size_t)h * ID_ + (size_t)(m0 + a_m) * lda;
        {
            float4 v = *reinterpret_cast<const float4*>(&A[a_k]);
            As[0][a_k+0][a_m]=v.x; As[0][a_k+1][a_m]=v.y; As[0][a_k+2][a_m]=v.z; As[0][a_k+3][a_m]=v.w;
        }
        __syncthreads();
        u64 tacc[8][2];
        #pragma unroll
        for (int i = 0; i < 8; i++) { tacc[i][0] = 0ull; tacc[i][1] = 0ull; }
        int buf = 0;
        for (int k0 = 0; k0 < 128; k0 += 8) {
            float4 v;
            bool nxt = (k0 + 8) < 128;
            if (nxt) v = *reinterpret_cast<const float4*>(&A[k0 + 8 + a_k]);
            #pragma unroll
            for (int k = 0; k < 8; k++) {
                float4 a0 = *reinterpret_cast<const float4*>(&As[buf][k][ty * 8]);
                float4 a1 = *reinterpret_cast<const float4*>(&As[buf][k][ty * 8 + 4]);
                float4 b0 = *reinterpret_cast<const float4*>(&Bs[k0 + k][tx * 4]);
                u64 bb[2] = {pack2(b0.x,b0.y), pack2(b0.z,b0.w)};
                float ra[8] = {a0.x,a0.y,a0.z,a0.w,a1.x,a1.y,a1.z,a1.w};
                #pragma unroll
                for (int i = 0; i < 8; i++) {
                    u64 aa = pack2(ra[i], ra[i]);
                    ffma2(tacc[i][0], aa, bb[0]);
                    ffma2(tacc[i][1], aa, bb[1]);
                }
            }
            if (nxt) {
                int nb = buf ^ 1;
                As[nb][a_k+0][a_m]=v.x; As[nb][a_k+1][a_m]=v.y; As[nb][a_k+2][a_m]=v.z; As[nb][a_k+3][a_m]=v.w;
                __syncthreads();
                buf = nb;
            }
        }
        __syncthreads();
        #pragma unroll
        for (int i = 0; i < 8; i++) {
            float w = g_ckvx[(size_t)(m0 + ty * 8 + i) * CKVX_ + 576 + h];  // iw (0.25 baked in)
            float2 t01 = unpack2(tacc[i][0]);
            float2 t23 = unpack2(tacc[i][1]);
            float tv[4] = {t01.x, t01.y, t23.x, t23.y};
            #pragma unroll
            for (int j = 0; j < 4; j++) {
                float add = __fmul_rn(w, fmaxf(tv[j], 0.f));
                sacc[i][j] = __fadd_rn(sacc[i][j], add);
            }
        }
    }
    #pragma unroll
    for (int i = 0; i < 8; i++) {
        int gm = m0 + ty * 8 + i;
        #pragma unroll
        for (int j = 0; j < 4; j++) {
            int gn = n0 + tx * 4 + j;
            g_scores[(size_t)gm * S_ + gn] = (gn <= gm) ? sacc[i][j] : NINF;
        }
    }
}

// ---------------- top-k (stable, jax tie semantics) ----------------
__device__ __forceinline__ unsigned fkey(float f) {
    unsigned u = __float_as_uint(f);
    return u ^ ((u >> 31) ? 0xFFFFFFFFu : 0x80000000u);
}

__global__ __launch_bounds__(256) void topk_kernel() {
    int q = blockIdx.x, t = threadIdx.x;
    const float* sc = g_scores + (size_t)q * S_;
    if (q < TOPK_) {
        for (int i = t; i <= q; i += 256) g_sel[(size_t)q * TOPK_ + i] = i;
        if (t == 0) g_nsel[q] = q + 1;
        return;
    }
    __shared__ unsigned hist[256];
    __shared__ unsigned s_pref, s_r;
    __shared__ int s_gt[257], s_eq[257];

    unsigned pref = 0, r = TOPK_;
    #pragma unroll
    for (int p = 3; p >= 0; p--) {
        hist[t] = 0;
        __syncthreads();
        for (int i = t; i < S_; i += 256) {
            unsigned u = fkey(sc[i]);
            bool ok = (p == 3) || ((u >> ((p + 1) * 8)) == pref);
            if (ok) atomicAdd(&hist[(u >> (p * 8)) & 255], 1u);
        }
        __syncthreads();
        if (t == 0) {
            unsigned run = 0;
            int b = 255;
            for (; b >= 0; b--) {
                unsigned c = hist[b];
                if (run + c >= r) break;
                run += c;
            }
            s_pref = (pref << 8) | (unsigned)b;
            s_r = r - run;
        }
        __syncthreads();
        pref = s_pref; r = s_r;
        __syncthreads();
    }
    unsigned T = pref;
    int need_eq = (int)r;

    int i0 = t * 8;
    unsigned keys[8];
    int cg = 0, ce = 0;
    #pragma unroll
    for (int k = 0; k < 8; k++) {
        unsigned u = fkey(sc[i0 + k]);
        keys[k] = u;
        cg += (u > T);
        ce += (u == T);
    }
    s_gt[t] = cg; s_eq[t] = ce;
    __syncthreads();
    if (t == 0) {
        int rg = 0, re = 0;
        for (int i = 0; i < 256; i++) {
            int a = s_gt[i]; s_gt[i] = rg; rg += a;
            int b2 = s_eq[i]; s_eq[i] = re; re += b2;
        }
        s_gt[256] = rg;
    }
    __syncthreads();
    int gpos = s_gt[t], epos = s_eq[t], total_gt = s_gt[256];
    int* out = g_sel + (size_t)q * TOPK_;
    #pragma unroll
    for (int k = 0; k < 8; k++) {
        unsigned u = keys[k];
        if (u > T) out[gpos++] = i0 + k;
        else if (u == T) {
            if (epos < need_eq) out[total_gt + epos] = i0 + k;
            epos++;
        }
    }
    if (t == 0) g_nsel[q] = TOPK_;
}

// ---------------- sparse attention (fp16 KV gather, fp32 math) ----------------
__global__ __launch_bounds__(128) void sparse_attn_kernel() {
    const float SCALE = 0.07216878364870322f;
    int qi = blockIdx.x, h = blockIdx.y;
    int t = threadIdx.x, w = t >> 5, lane = t & 31;
    __shared__ float qv[192];
    __shared__ float s_p[TOPK_];
    __shared__ int s_idx[TOPK_];
    __shared__ float s_red[4];
    __shared__ float s_out[4][128];

    int n = g_nsel[qi];
    const float* qptr = g_q + (size_t)qi * (H_ * 192) + h * 192;
    for (int i = t; i < 192; i += 128) qv[i] = qptr[i];
    for (int i = t; i < n; i += 128) s_idx[i] = g_sel[(size_t)qi * TOPK_ + i];
    __syncthreads();

    for (int j = w; j < n; j += 4) {
        int kidx = s_idx[j];
        const __half* kh = g_kvh + (size_t)kidx * (H_ * 256) + h * 256;
        uint2 raw = *reinterpret_cast<const uint2*>(kh + lane * 4);
        float2 f01 = __half22float2(*reinterpret_cast<const __half2*>(&raw.x));
        float2 f23 = __half22float2(*reinterpret_cast<const __half2*>(&raw.y));
        float4 a = reinterpret_cast<const float4*>(qv)[lane];
        float d = a.x * f01.x + a.y * f01.y + a.z * f23.x + a.w * f23.y;
        const float2* kp = reinterpret_cast<const float2*>(g_kpe + (size_t)kidx * ROPE_);
        float2 ap = reinterpret_cast<const float2*>(qv + 128)[lane];
        float2 bp = kp[lane];
        d += ap.x * bp.x + ap.y * bp.y;
        #pragma unroll
        for (int o = 16; o; o >>= 1) d += __shfl_down_sync(0xffffffffu, d, o);
        if (lane == 0) s_p[j] = d * SCALE;
    }
    __syncthreads();

    float m = -3.4e38f;
    for (int i = t; i < n; i += 128) m = fmaxf(m, s_p[i]);
    #pragma unroll
    for (int o = 16; o; o >>= 1) m = fmaxf(m, __shfl_xor_sync(0xffffffffu, m, o));
    if (lane == 0) s_red[w] = m;
    __syncthreads();
    m = fmaxf(fmaxf(s_red[0], s_red[1]), fmaxf(s_red[2], s_red[3]));
    __syncthreads();

    float sum = 0.f;
    for (int i = t; i < n; i += 128) {
        float e = __expf(s_p[i] - m);
        s_p[i] = e;
        sum += e;
    }
    #pragma unroll
    for (int o = 16; o; o >>= 1) sum += __shfl_xor_sync(0xffffffffu, sum, o);
    __syncthreads();
    if (lane == 0) s_red[w] = sum;
    __syncthreads();
    sum = s_red[0] + s_red[1] + s_red[2] + s_red[3];
    float inv = 1.0f / sum;

    float4 acc = make_float4(0.f, 0.f, 0.f, 0.f);
    for (int j = w; j < n; j += 4) {
        float p = s_p[j];
        int kidx = s_idx[j];
        const __half* vh = g_kvh + (size_t)kidx * (H_ * 256) + h * 256 + 128;
        uint2 raw = *reinterpret_cast<const uint2*>(vh + lane * 4);
        float2 v01 = __half22float2(*reinterpret_cast<const __half2*>(&raw.x));
        float2 v23 = __half22float2(*reinterpret_cast<const __half2*>(&raw.y));
        acc.x += p * v01.x; acc.y += p * v01.y; acc.z += p * v23.x; acc.w += p * v23.y;
    }
    reinterpret_cast<float4*>(&s_out[w][0])[lane] = acc;
    __syncthreads();
    float o = (s_out[0][t] + s_out[1][t] + s_out[2][t] + s_out[3][t]) * inv;
    g_attn[(size_t)qi * (H_ * VDIM_) + h * VDIM_ + t] = o;
}

// ---------------- launch ----------------
extern "C" void kernel_launch(void* const* d_in, const int* in_sizes, int n_in,
                              void* d_out, int out_size) {
    (void)in_sizes; (void)n_in; (void)out_size;
    const float* hidden      = (const float*)d_in[0];
    const float* q_a_w       = (const float*)d_in[1];
    const float* q_a_ln_w    = (const float*)d_in[2];
    const float* q_b_w       = (const float*)d_in[3];
    const float* kv_a_w      = (const float*)d_in[4];
    const float* kv_a_ln_w   = (const float*)d_in[5];
    const float* kv_b_w      = (const float*)d_in[6];
    const float* o_w         = (const float*)d_in[7];
    const float* idx_wq_b_w  = (const float*)d_in[8];
    const float* idx_wk_w    = (const float*)d_in[9];
    const float* idx_kn_w    = (const float*)d_in[10];
    const float* idx_kn_b    = (const float*)d_in[11];
    const float* idx_wproj_w = (const float*)d_in[12];
    float* out = (float*)d_out;

    float *p_qr, *p_q, *p_iq, *p_ikpre, *p_attn;
    cudaGetSymbolAddress((void**)&p_qr,    g_qr);
    cudaGetSymbolAddress((void**)&p_q,     g_q);
    cudaGetSymbolAddress((void**)&p_iq,    g_iq);
    cudaGetSymbolAddress((void**)&p_ikpre, g_ikpre);
    cudaGetSymbolAddress((void**)&p_attn,  g_attn);

    dim3 tb(256);

    cossin_kernel<<<S_, 32>>>();
    build_bext_kernel<<<(CKVX_ * HID_ / 4 + 255) / 256, 256>>>(kv_a_w, idx_wproj_w);

    // qr | ckvx(incl 0.25*iw) | ik — 288 blocks, single wave over A=hidden (K=2048)
    fused_hidden_gemm<<<dim3(18, S_ / 128), tb>>>(hidden, q_a_w, idx_wk_w);
    rmsnorm_kernel<<<S_, 256>>>(p_qr, q_a_ln_w, QR_);
    ckv_split_kernel<<<S_, 256>>>(kv_a_ln_w);
    ik_ln_rope_kernel<<<S_, 128>>>(p_ikpre, idx_kn_w, idx_kn_b);

    // q | iq (K=1536) with kv_b (K=512, fp16 out) backfilling the tail wave
    fused_qr_kv_gemm<<<dim3(72, S_ / 128), tb>>>(q_b_w, idx_wq_b_w, kv_b_w);

    // rope q_pe and iq
    rope_kernel<<<S_, dim3(32, H_)>>>(p_q + NOPE_, H_ * 192, 192);
    rope_kernel<<<S_, dim3(32, IH_)>>>(p_iq, IH_ * ID_, ID_);

    // fused indexer scores (causal skip + FFMA2)
    idx_scores_kernel<<<dim3(S_ / 64, S_ / 128), tb>>>();

    topk_kernel<<<S_, 256>>>();

    sparse_attn_kernel<<<dim3(S_, H_), 128>>>();

    // out = attn @ o_w^T   [S, 2048]
    sgemm_nt_db<<<dim3(HID_ / 128, S_ / 128), tb>>>(p_attn, H_ * VDIM_, o_w, H_ * VDIM_, out, HID_, S_, HID_, H_ * VDIM_, 1.f);
}